// round 3
// baseline (speedup 1.0000x reference)
#include <cuda_runtime.h>
#include <cuda_fp16.h>

// ---------------- problem constants ----------------
#define TOK     32
#define KDIM    4096
#define NDIM    11008
#define NTILE   64                 // output columns per CTA
#define NCHUNK  64                 // 64 k-chunks of 64 (== quant group size)
#define KWORDS  2048               // int32 words per packed row
#define GRID_N  (NDIM / NTILE)     // 172 CTAs

// x split into fp16 hi/lo parts: rows 0-31 = hi(t), rows 32-63 = lo(t)
__device__ __half g_xparts[64 * KDIM];
// per-(token, group) sums of fp32 x
__device__ float  g_xsum[TOK * NCHUNK];

// ---------------- prep kernel ----------------
// grid 32 (one block per token), block 256
__global__ void awq_prep_kernel(const float* __restrict__ x) {
    const int t   = blockIdx.x;
    const int tid = threadIdx.x;
    const float* xr = x + (size_t)t * KDIM;
    float psum = 0.f;
#pragma unroll
    for (int u = 0; u < 16; ++u) {
        int k = tid * 16 + u;
        float v = xr[k];
        __half h = __float2half_rn(v);
        float fh = __half2float(h);
        g_xparts[(size_t)t * KDIM + k] = h;
        g_xparts[(size_t)(t + 32) * KDIM + k] = __float2half_rn(v - fh);
        psum += v;
    }
    // 4 threads cover one 64-wide group (16 elems each) -> reduce
    psum += __shfl_xor_sync(0xFFFFFFFFu, psum, 1);
    psum += __shfl_xor_sync(0xFFFFFFFFu, psum, 2);
    if ((tid & 3) == 0) g_xsum[t * NCHUNK + (tid >> 2)] = psum;
}

// ---------------- mma helpers ----------------
static __device__ __forceinline__ unsigned smem_u32(const void* p) {
    unsigned a;
    asm("{ .reg .u64 t; cvta.to.shared.u64 t, %1; cvt.u32.u64 %0, t; }"
        : "=r"(a) : "l"(p));
    return a;
}
static __device__ __forceinline__ void ldmatrix_x4(unsigned& a0, unsigned& a1,
                                                   unsigned& a2, unsigned& a3,
                                                   unsigned addr) {
    asm volatile("ldmatrix.sync.aligned.m8n8.x4.shared.b16 {%0,%1,%2,%3}, [%4];"
                 : "=r"(a0), "=r"(a1), "=r"(a2), "=r"(a3) : "r"(addr));
}
static __device__ __forceinline__ void mma16816(float& d0, float& d1, float& d2, float& d3,
                                                unsigned a0, unsigned a1, unsigned a2, unsigned a3,
                                                unsigned b0, unsigned b1) {
    asm volatile("mma.sync.aligned.m16n8k16.row.col.f32.f16.f16.f32 "
                 "{%0,%1,%2,%3}, {%4,%5,%6,%7}, {%8,%9}, {%0,%1,%2,%3};"
                 : "+f"(d0), "+f"(d1), "+f"(d2), "+f"(d3)
                 : "r"(a0), "r"(a1), "r"(a2), "r"(a3), "r"(b0), "r"(b1));
}

// fp16 magic: value = 16 + q  (exact: 16+q in [16,31], ulp(16)=1/64, q<<6 mantissa)
static __device__ __forceinline__ unsigned bpack(unsigned t) {
    return 0x4C004C00u | ((t & 0xFu) << 6) | ((t & 0xF0u) << 18);
}

// ---------------- main kernel ----------------
#define A_STRIDE 144   // 64 fp16 = 128B + 16B pad (conflict-free ldmatrix)

struct Stage {
    int    q[8];
    float2 s, z;
    uint4  a0, a1;
};

static __device__ __forceinline__ void load_stage(Stage& st, int i,
        const int* __restrict__ qb, const float* __restrict__ sp,
        const float* __restrict__ zp, const uint4* __restrict__ ap) {
#pragma unroll
    for (int u = 0; u < 8; ++u) st.q[u] = qb[i * 32 + 4 * u];
    st.s = *reinterpret_cast<const float2*>(sp + (size_t)i * NDIM);
    st.z = *reinterpret_cast<const float2*>(zp + (size_t)i * NDIM);
    st.a0 = ap[i * 8];
    st.a1 = ap[i * 8 + 1];
}

__global__ void __launch_bounds__(256, 2)
awq_main_kernel(const int* __restrict__ qweight,
                const float* __restrict__ wscales,
                const float* __restrict__ wzeros,
                const float* __restrict__ bias,
                float* __restrict__ out) {
    __shared__ __align__(16) char sA[2][64 * A_STRIDE];   // 18432 B
    __shared__ float sX[32 * 65];                          // 8320 B

    const int tid  = threadIdx.x;
    const int wid  = tid >> 5;
    const int lane = tid & 31;
    const int n0   = blockIdx.x * NTILE;

    // ---- B-side addressing: warp owns n-slice [n0 + wid*8, +8) ----
    const int nB   = n0 + wid * 8 + (lane >> 2);       // n for B fragment
    const int np   = nB >> 2;                          // packed row
    const unsigned sh = (unsigned)((nB & 3) * 8);      // byte of the word
    const int* qb = qweight + (size_t)np * KWORDS + (lane & 3);

    // ---- accumulator-side n: n0 + wid*8 + 2*(lane&3) + {0,1} ----
    const int nS = n0 + wid * 8 + 2 * (lane & 3);
    const float* sp = wscales + nS;
    const float* zp = wzeros + nS;

    // ---- A staging: thread copies row r, 32B piece p, per chunk ----
    const int ar = tid >> 2;
    const int apc = tid & 3;
    const uint4* ap = reinterpret_cast<const uint4*>(
        g_xparts + (size_t)ar * KDIM + apc * 16);
    const unsigned aw_off = (unsigned)(ar * A_STRIDE + apc * 32);

    // ---- load X sums into smem (padded stride 65) ----
#pragma unroll
    for (int v = 0; v < 8; ++v) {
        int idx = tid * 8 + v;
        sX[(idx >> 6) * 65 + (idx & 63)] = g_xsum[idx];
    }
    const float2 bs = *reinterpret_cast<const float2*>(bias + nS);

    Stage st[2];
    load_stage(st[0], 0, qb, sp, zp, ap);
    {
        unsigned w0 = smem_u32(&sA[0][0]) + aw_off;
        *reinterpret_cast<uint4*>(&sA[0][0] + aw_off) = st[0].a0;
        *reinterpret_cast<uint4*>(&sA[0][0] + aw_off + 16) = st[0].a1;
        (void)w0;
    }
    __syncthreads();

    float fin[4][4];
    float corr[2][4];
#pragma unroll
    for (int m = 0; m < 4; ++m)
#pragma unroll
        for (int c = 0; c < 4; ++c) fin[m][c] = 0.f;
#pragma unroll
    for (int m = 0; m < 2; ++m)
#pragma unroll
        for (int c = 0; c < 4; ++c) corr[m][c] = 0.f;

    const unsigned a_lbase = (unsigned)((lane & 15) * A_STRIDE + (lane >> 4) * 16);

    for (int i = 0; i < NCHUNK; ++i) {
        const int b = i & 1;
        Stage& cur = st[b];
        if (i + 1 < NCHUNK) load_stage(st[b ^ 1], i + 1, qb, sp, zp, ap);

        const unsigned Ab = smem_u32(&sA[b][0]) + a_lbase;
        float acc[4][4];
#pragma unroll
        for (int m = 0; m < 4; ++m)
#pragma unroll
            for (int c = 0; c < 4; ++c) acc[m][c] = 0.f;

#pragma unroll
        for (int s4 = 0; s4 < 4; ++s4) {
            const unsigned b0 = bpack(((unsigned)cur.q[2 * s4]) >> sh);
            const unsigned b1 = bpack(((unsigned)cur.q[2 * s4 + 1]) >> sh);
#pragma unroll
            for (int mt = 0; mt < 4; ++mt) {
                unsigned a0, a1, a2, a3;
                ldmatrix_x4(a0, a1, a2, a3,
                            Ab + (unsigned)(mt * 16 * A_STRIDE + s4 * 32));
                mma16816(acc[mt][0], acc[mt][1], acc[mt][2], acc[mt][3],
                         a0, a1, a2, a3, b0, b1);
            }
        }

        // per-group scale into final accumulators
        const float s0 = cur.s.x, s1 = cur.s.y;
#pragma unroll
        for (int mt = 0; mt < 4; ++mt) {
            fin[mt][0] = fmaf(s0, acc[mt][0], fin[mt][0]);
            fin[mt][1] = fmaf(s1, acc[mt][1], fin[mt][1]);
            fin[mt][2] = fmaf(s0, acc[mt][2], fin[mt][2]);
            fin[mt][3] = fmaf(s1, acc[mt][3], fin[mt][3]);
        }
        // correction term: sum_g s*(16+z)*X[t,g]
        const float u0 = s0 * (cur.z.x + 16.f);
        const float u1 = s1 * (cur.z.y + 16.f);
        float Xv[4];
#pragma unroll
        for (int jj = 0; jj < 4; ++jj)
            Xv[jj] = sX[((lane >> 2) + 8 * jj) * 65 + i];
#pragma unroll
        for (int mp = 0; mp < 2; ++mp) {
            corr[mp][0] = fmaf(u0, Xv[mp * 2 + 0], corr[mp][0]);
            corr[mp][1] = fmaf(u1, Xv[mp * 2 + 0], corr[mp][1]);
            corr[mp][2] = fmaf(u0, Xv[mp * 2 + 1], corr[mp][2]);
            corr[mp][3] = fmaf(u1, Xv[mp * 2 + 1], corr[mp][3]);
        }

        if (i + 1 < NCHUNK) {
            char* dst = &sA[b ^ 1][0] + aw_off;
            *reinterpret_cast<uint4*>(dst) = st[b ^ 1].a0;
            *reinterpret_cast<uint4*>(dst + 16) = st[b ^ 1].a1;
        }
        __syncthreads();
    }

    // ---- epilogue: combine hi (rows 0-31) + lo (rows 32-63), subtract corr ----
#pragma unroll
    for (int mp = 0; mp < 2; ++mp) {
#pragma unroll
        for (int cp = 0; cp < 2; ++cp) {
            int t = mp * 16 + (lane >> 2) + cp * 8;
            float2 o;
            o.x = fin[mp][cp * 2 + 0] + fin[mp + 2][cp * 2 + 0]
                  - corr[mp][cp * 2 + 0] + bs.x;
            o.y = fin[mp][cp * 2 + 1] + fin[mp + 2][cp * 2 + 1]
                  - corr[mp][cp * 2 + 1] + bs.y;
            *reinterpret_cast<float2*>(out + (size_t)t * NDIM + nS) = o;
        }
    }
}

// ---------------- launch ----------------
extern "C" void kernel_launch(void* const* d_in, const int* in_sizes, int n_in,
                              void* d_out, int out_size) {
    const float* x       = (const float*)d_in[0];
    const int*   qweight = (const int*)d_in[1];
    const float* wscales = (const float*)d_in[2];
    const float* wzeros  = (const float*)d_in[3];
    const float* bias    = (const float*)d_in[4];
    float* out = (float*)d_out;
    (void)in_sizes; (void)n_in; (void)out_size;

    awq_prep_kernel<<<TOK, 256>>>(x);
    awq_main_kernel<<<GRID_N, 256>>>(qweight, wscales, wzeros, bias, out);
}

// round 4
// speedup vs baseline: 2.2551x; 2.2551x over previous
#include <cuda_runtime.h>
#include <cuda_fp16.h>

// ---------------- problem constants ----------------
#define TOK      32
#define KDIM     4096
#define NDIM     11008
#define NTILE    64                  // output columns per CTA
#define GRID_N   (NDIM / NTILE)      // 172
#define SPLITK   4
#define NCHUNK_G 64                  // total k-chunks of 64 (== group size)
#define CPC      (NCHUNK_G / SPLITK) // 16 chunks per CTA
#define KWORDS   2048                // int32 words per packed row
#define A_STRIDE 144                 // 128B row + 16B pad (conflict-free ldmatrix)

// x split into fp16 hi/lo parts, k PERMUTED within each 64-group:
// orig col c (=k>>1) in [0,32): chat = (c>>3) + 4*(c&7); khat = 2*chat + (k&1)
__device__ __half g_xparts[64 * KDIM];
__device__ float  g_xsum[TOK * NCHUNK_G];
__device__ float  g_partial[SPLITK][TOK * NDIM];

// ---------------- prep kernel: split + permute x, group sums ----------------
// grid TOK, block 256; thread handles 16 contiguous k
__global__ void awq_prep_kernel(const float* __restrict__ x) {
    const int t   = blockIdx.x;
    const int tid = threadIdx.x;
    const float* xr = x + (size_t)t * KDIM;
    float psum = 0.f;
#pragma unroll
    for (int u = 0; u < 16; u += 2) {
        int k = tid * 16 + u;                    // even
        float v0 = xr[k], v1 = xr[k + 1];
        int c = (k & 63) >> 1;
        int chat = (c >> 3) + 4 * (c & 7);
        int khat = (k & ~63) + 2 * chat;
        __half h0 = __float2half_rn(v0), h1 = __float2half_rn(v1);
        *reinterpret_cast<__half2*>(g_xparts + (size_t)t * KDIM + khat) =
            __halves2half2(h0, h1);
        *reinterpret_cast<__half2*>(g_xparts + (size_t)(t + 32) * KDIM + khat) =
            __halves2half2(__float2half_rn(v0 - __half2float(h0)),
                           __float2half_rn(v1 - __half2float(h1)));
        psum += v0 + v1;
    }
    psum += __shfl_xor_sync(0xFFFFFFFFu, psum, 1);
    psum += __shfl_xor_sync(0xFFFFFFFFu, psum, 2);
    if ((tid & 3) == 0) g_xsum[t * NCHUNK_G + (tid >> 2)] = psum;
}

// ---------------- helpers ----------------
static __device__ __forceinline__ unsigned smem_u32(const void* p) {
    unsigned a;
    asm("{ .reg .u64 t; cvta.to.shared.u64 t, %1; cvt.u32.u64 %0, t; }"
        : "=r"(a) : "l"(p));
    return a;
}
static __device__ __forceinline__ void ldmatrix_x4(unsigned& a0, unsigned& a1,
                                                   unsigned& a2, unsigned& a3,
                                                   unsigned addr) {
    asm volatile("ldmatrix.sync.aligned.m8n8.x4.shared.b16 {%0,%1,%2,%3}, [%4];"
                 : "=r"(a0), "=r"(a1), "=r"(a2), "=r"(a3) : "r"(addr));
}
static __device__ __forceinline__ void mma16816(float& d0, float& d1, float& d2, float& d3,
                                                unsigned a0, unsigned a1, unsigned a2, unsigned a3,
                                                unsigned b0, unsigned b1) {
    asm volatile("mma.sync.aligned.m16n8k16.row.col.f32.f16.f16.f32 "
                 "{%0,%1,%2,%3}, {%4,%5,%6,%7}, {%8,%9}, {%0,%1,%2,%3};"
                 : "+f"(d0), "+f"(d1), "+f"(d2), "+f"(d3)
                 : "r"(a0), "r"(a1), "r"(a2), "r"(a3), "r"(b0), "r"(b1));
}
// fp16 value = 16 + q, bit-exact: 0x4C00 | (q<<6)
static __device__ __forceinline__ unsigned bpack(unsigned t) {
    return 0x4C004C00u | ((t & 0xFu) << 6) | ((t & 0xF0u) << 18);
}

// ---------------- main kernel ----------------
struct Stage {
    int4   q0, q1;   // 8 contiguous packed words (thread's own, post-permute)
    uint4  a0, a1;   // 32B of A chunk to stage
    float2 s, z;
};

static __device__ __forceinline__ void load_stage(Stage& st, int i,
        const int* __restrict__ qb, const float* __restrict__ sp,
        const float* __restrict__ zp, const uint4* __restrict__ ap) {
    st.q0 = *reinterpret_cast<const int4*>(qb + i * 32);
    st.q1 = *reinterpret_cast<const int4*>(qb + i * 32 + 4);
    st.a0 = ap[i * 8];
    st.a1 = ap[i * 8 + 1];
    st.s  = *reinterpret_cast<const float2*>(sp + (size_t)i * NDIM);
    st.z  = *reinterpret_cast<const float2*>(zp + (size_t)i * NDIM);
}

__global__ void __launch_bounds__(256, 2)
awq_main_kernel(const int* __restrict__ qweight,
                const float* __restrict__ wscales,
                const float* __restrict__ wzeros,
                const float* __restrict__ bias) {
    __shared__ __align__(16) char sA[2][64 * A_STRIDE];   // 18432 B
    __shared__ float sX[32 * 17];                          // 2176 B

    const int tid  = threadIdx.x;
    const int wid  = tid >> 5;
    const int lane = tid & 31;
    const int n0   = blockIdx.x * NTILE;
    const int kb   = blockIdx.y;
    const int g0   = kb * CPC;

    // ---- B-side: fragment n = n0 + wid*8 + (lane>>2) ----
    const int np      = (n0 >> 2) + 2 * wid + (lane >> 4);   // packed row
    const unsigned sh = 8u * ((lane >> 2) & 3);              // byte select
    const int* qb = qweight + (size_t)np * KWORDS + g0 * 32 + 8 * (lane & 3);

    // ---- accumulator-side n ----
    const int nS = n0 + wid * 8 + 2 * (lane & 3);
    const float* sp = wscales + (size_t)g0 * NDIM + nS;
    const float* zp = wzeros  + (size_t)g0 * NDIM + nS;

    // ---- A staging addressing ----
    const int ar = tid >> 2, apc = tid & 3;
    const uint4* ap = reinterpret_cast<const uint4*>(
        g_xparts + (size_t)ar * KDIM + g0 * 64 + apc * 16);
    const unsigned aw_off = (unsigned)(ar * A_STRIDE + apc * 32);

    // ---- X sums slice for this k-split ----
    {
        int idx = tid * 2;
        sX[(idx >> 4) * 17 + (idx & 15)] = g_xsum[(idx >> 4) * NCHUNK_G + g0 + (idx & 15)];
        idx++;
        sX[(idx >> 4) * 17 + (idx & 15)] = g_xsum[(idx >> 4) * NCHUNK_G + g0 + (idx & 15)];
    }
    float2 bs = make_float2(0.f, 0.f);
    if (kb == 0) bs = *reinterpret_cast<const float2*>(bias + nS);

    Stage st[3];
    load_stage(st[0], 0, qb, sp, zp, ap);
    load_stage(st[1], 1, qb, sp, zp, ap);
    {
        char* dst = &sA[0][0] + aw_off;
        *reinterpret_cast<uint4*>(dst)      = st[0].a0;
        *reinterpret_cast<uint4*>(dst + 16) = st[0].a1;
    }
    __syncthreads();

    float fin[4][4];
#pragma unroll
    for (int m = 0; m < 4; ++m)
#pragma unroll
        for (int c = 0; c < 4; ++c) fin[m][c] = 0.f;

    const unsigned a_lbase = (unsigned)((lane & 15) * A_STRIDE + (lane >> 4) * 16);

#pragma unroll
    for (int i = 0; i < CPC; ++i) {
        const int cb = i & 1;
        Stage& cur = st[i % 3];
        if (i + 2 < CPC) load_stage(st[(i + 2) % 3], i + 2, qb, sp, zp, ap);

        const unsigned Ab = smem_u32(&sA[cb][0]) + a_lbase;
        float acc[4][4];
#pragma unroll
        for (int m = 0; m < 4; ++m)
#pragma unroll
            for (int c = 0; c < 4; ++c) acc[m][c] = 0.f;

        const int qa[8] = { cur.q0.x, cur.q0.y, cur.q0.z, cur.q0.w,
                            cur.q1.x, cur.q1.y, cur.q1.z, cur.q1.w };
#pragma unroll
        for (int s4 = 0; s4 < 4; ++s4) {
            const unsigned b0 = bpack(((unsigned)qa[2 * s4])     >> sh);
            const unsigned b1 = bpack(((unsigned)qa[2 * s4 + 1]) >> sh);
#pragma unroll
            for (int mt = 0; mt < 4; ++mt) {
                unsigned a0, a1, a2, a3;
                ldmatrix_x4(a0, a1, a2, a3,
                            Ab + (unsigned)(mt * 16 * A_STRIDE + s4 * 32));
                mma16816(acc[mt][0], acc[mt][1], acc[mt][2], acc[mt][3],
                         a0, a1, a2, a3, b0, b1);
            }
        }

        // per-group scale into final accumulators
        const float s0 = cur.s.x, s1 = cur.s.y;
#pragma unroll
        for (int mt = 0; mt < 4; ++mt) {
            fin[mt][0] = fmaf(s0, acc[mt][0], fin[mt][0]);
            fin[mt][1] = fmaf(s1, acc[mt][1], fin[mt][1]);
            fin[mt][2] = fmaf(s0, acc[mt][2], fin[mt][2]);
            fin[mt][3] = fmaf(s1, acc[mt][3], fin[mt][3]);
        }
        // correction: fin(hi rows) -= s*(16+z) * X[t, group]
        const float u0 = s0 * (cur.z.x + 16.f);
        const float u1 = s1 * (cur.z.y + 16.f);
        float Xv[4];
#pragma unroll
        for (int jj = 0; jj < 4; ++jj)
            Xv[jj] = sX[((lane >> 2) + 8 * jj) * 17 + i];
#pragma unroll
        for (int mp = 0; mp < 2; ++mp) {
            fin[mp][0] = fmaf(-u0, Xv[mp * 2 + 0], fin[mp][0]);
            fin[mp][1] = fmaf(-u1, Xv[mp * 2 + 0], fin[mp][1]);
            fin[mp][2] = fmaf(-u0, Xv[mp * 2 + 1], fin[mp][2]);
            fin[mp][3] = fmaf(-u1, Xv[mp * 2 + 1], fin[mp][3]);
        }

        if (i + 1 < CPC) {
            Stage& nx = st[(i + 1) % 3];
            char* dst = &sA[cb ^ 1][0] + aw_off;
            *reinterpret_cast<uint4*>(dst)      = nx.a0;
            *reinterpret_cast<uint4*>(dst + 16) = nx.a1;
        }
        __syncthreads();
    }

    // ---- epilogue: combine hi (rows 0-31) + lo (rows 32-63) ----
    float* part = &g_partial[kb][0];
#pragma unroll
    for (int mp = 0; mp < 2; ++mp) {
#pragma unroll
        for (int cp = 0; cp < 2; ++cp) {
            int t = mp * 16 + (lane >> 2) + cp * 8;
            float2 o;
            o.x = fin[mp][cp * 2 + 0] + fin[mp + 2][cp * 2 + 0] + bs.x;
            o.y = fin[mp][cp * 2 + 1] + fin[mp + 2][cp * 2 + 1] + bs.y;
            *reinterpret_cast<float2*>(part + (size_t)t * NDIM + nS) = o;
        }
    }
}

// ---------------- combine kernel ----------------
__global__ void awq_combine_kernel(float* __restrict__ out) {
    const int j = blockIdx.x * 256 + threadIdx.x;   // < 88064
    const float4* p0 = reinterpret_cast<const float4*>(g_partial[0]);
    const float4* p1 = reinterpret_cast<const float4*>(g_partial[1]);
    const float4* p2 = reinterpret_cast<const float4*>(g_partial[2]);
    const float4* p3 = reinterpret_cast<const float4*>(g_partial[3]);
    float4 a = p0[j], b = p1[j], c = p2[j], d = p3[j];
    float4 r;
    r.x = (a.x + b.x) + (c.x + d.x);
    r.y = (a.y + b.y) + (c.y + d.y);
    r.z = (a.z + b.z) + (c.z + d.z);
    r.w = (a.w + b.w) + (c.w + d.w);
    reinterpret_cast<float4*>(out)[j] = r;
}

// ---------------- launch ----------------
extern "C" void kernel_launch(void* const* d_in, const int* in_sizes, int n_in,
                              void* d_out, int out_size) {
    const float* x       = (const float*)d_in[0];
    const int*   qweight = (const int*)d_in[1];
    const float* wscales = (const float*)d_in[2];
    const float* wzeros  = (const float*)d_in[3];
    const float* bias    = (const float*)d_in[4];
    float* out = (float*)d_out;
    (void)in_sizes; (void)n_in; (void)out_size;

    awq_prep_kernel<<<TOK, 256>>>(x);
    awq_main_kernel<<<dim3(GRID_N, SPLITK), 256>>>(qweight, wscales, wzeros, bias);
    awq_combine_kernel<<<(TOK * NDIM) / (256 * 4), 256>>>(out);
}

// round 5
// speedup vs baseline: 3.4890x; 1.5472x over previous
#include <cuda_runtime.h>
#include <cuda_fp16.h>

// ---------------- problem constants ----------------
#define TOK      32
#define KDIM     4096
#define NDIM     11008
#define NTILE    64                  // output columns per CTA
#define GRID_N   (NDIM / NTILE)      // 172
#define SPLITK   8
#define NCHUNK_G 64                  // total k-chunks of 64 (== group size)
#define CPC      (NCHUNK_G / SPLITK) // 8 chunks per CTA
#define KWORDS   2048                // int32 words per packed row
#define A_STRIDE 144                 // 128B row + 16B pad (conflict-free ldmatrix)

// x in fp16 (hi only), k PERMUTED within each 64-group:
// orig col c (=k>>1 within group) in [0,32): chat = (c>>3) + 4*(c&7)
__device__ __half g_xparts[TOK * KDIM];
// per-(token, group) sums of the fp16-ROUNDED x (fp32 accumulated) ->
// makes the +16 weight offset cancel exactly.
__device__ float  g_xsum[TOK * NCHUNK_G];
__device__ float  g_partial[SPLITK][TOK * NDIM];

// ---------------- prep kernel ----------------
// grid 128 (4 blocks per token), block 256; thread handles 4 contiguous k
__global__ void awq_prep_kernel(const float* __restrict__ x) {
    const int blk = blockIdx.x;
    const int tid = threadIdx.x;
    const int t   = blk >> 2;
    const int k0  = (blk & 3) * 1024 + tid * 4;
    float4 v = *reinterpret_cast<const float4*>(x + (size_t)t * KDIM + k0);

    __half h0 = __float2half_rn(v.x), h1 = __float2half_rn(v.y);
    __half h2 = __float2half_rn(v.z), h3 = __float2half_rn(v.w);

    // permuted destinations (pairs of even k)
    int c0 = (k0 & 63) >> 1;
    int c1 = c0 + 1;
    int chat0 = (c0 >> 3) + 4 * (c0 & 7);
    int chat1 = (c1 >> 3) + 4 * (c1 & 7);
    int base  = (k0 & ~63) + ((size_t)0);
    __half* xp = g_xparts + (size_t)t * KDIM + (k0 & ~63u);
    *reinterpret_cast<__half2*>(xp + 2 * chat0) = __halves2half2(h0, h1);
    *reinterpret_cast<__half2*>(xp + 2 * chat1) = __halves2half2(h2, h3);
    (void)base;

    // group sum of the ROUNDED values
    float psum = __half2float(h0) + __half2float(h1)
               + __half2float(h2) + __half2float(h3);
    psum += __shfl_xor_sync(0xFFFFFFFFu, psum, 1);
    psum += __shfl_xor_sync(0xFFFFFFFFu, psum, 2);
    psum += __shfl_xor_sync(0xFFFFFFFFu, psum, 4);
    psum += __shfl_xor_sync(0xFFFFFFFFu, psum, 8);
    if ((tid & 15) == 0) {
        int grp = (blk & 3) * 16 + (tid >> 4);
        g_xsum[t * NCHUNK_G + grp] = psum;
    }
}

// ---------------- helpers ----------------
static __device__ __forceinline__ unsigned smem_u32(const void* p) {
    unsigned a;
    asm("{ .reg .u64 t; cvta.to.shared.u64 t, %1; cvt.u32.u64 %0, t; }"
        : "=r"(a) : "l"(p));
    return a;
}
static __device__ __forceinline__ void ldmatrix_x4(unsigned& a0, unsigned& a1,
                                                   unsigned& a2, unsigned& a3,
                                                   unsigned addr) {
    asm volatile("ldmatrix.sync.aligned.m8n8.x4.shared.b16 {%0,%1,%2,%3}, [%4];"
                 : "=r"(a0), "=r"(a1), "=r"(a2), "=r"(a3) : "r"(addr));
}
static __device__ __forceinline__ void mma16816(float& d0, float& d1, float& d2, float& d3,
                                                unsigned a0, unsigned a1, unsigned a2, unsigned a3,
                                                unsigned b0, unsigned b1) {
    asm volatile("mma.sync.aligned.m16n8k16.row.col.f32.f16.f16.f32 "
                 "{%0,%1,%2,%3}, {%4,%5,%6,%7}, {%8,%9}, {%0,%1,%2,%3};"
                 : "+f"(d0), "+f"(d1), "+f"(d2), "+f"(d3)
                 : "r"(a0), "r"(a1), "r"(a2), "r"(a3), "r"(b0), "r"(b1));
}
// fp16 value = 16 + q, bit-exact: 0x4C00 | (q<<6)
static __device__ __forceinline__ unsigned bpack(unsigned t) {
    return 0x4C004C00u | ((t & 0xFu) << 6) | ((t & 0xF0u) << 18);
}

// ---------------- main kernel ----------------
struct Stage {
    int4  q0, q1;   // 8 contiguous packed words (thread's own, post-permute)
    uint4 a;        // 16B of A chunk to stage
    float2 s, z;
};

static __device__ __forceinline__ void load_stage(Stage& st, int i,
        const int* __restrict__ qb, const float* __restrict__ sp,
        const float* __restrict__ zp, const uint4* __restrict__ ap) {
    st.q0 = *reinterpret_cast<const int4*>(qb + i * 32);
    st.q1 = *reinterpret_cast<const int4*>(qb + i * 32 + 4);
    st.a  = ap[i * 8];
    st.s  = *reinterpret_cast<const float2*>(sp + (size_t)i * NDIM);
    st.z  = *reinterpret_cast<const float2*>(zp + (size_t)i * NDIM);
}

__global__ void __launch_bounds__(256, 3)
awq_main_kernel(const int* __restrict__ qweight,
                const float* __restrict__ wscales,
                const float* __restrict__ wzeros,
                const float* __restrict__ bias) {
    __shared__ __align__(16) char sA[2][32 * A_STRIDE];   // 9216 B
    __shared__ float sX[32 * 9];                           // 1152 B

    const int tid  = threadIdx.x;
    const int wid  = tid >> 5;
    const int lane = tid & 31;
    const int n0   = blockIdx.x * NTILE;
    const int kb   = blockIdx.y;
    const int g0   = kb * CPC;

    // ---- B-side: fragment n = n0 + wid*8 + (lane>>2) ----
    const int np      = (n0 >> 2) + 2 * wid + (lane >> 4);   // packed row
    const unsigned sh = 8u * ((lane >> 2) & 3);              // byte select
    const int* qb = qweight + (size_t)np * KWORDS + g0 * 32 + 8 * (lane & 3);

    // ---- accumulator-side n ----
    const int nS = n0 + wid * 8 + 2 * (lane & 3);
    const float* sp = wscales + (size_t)g0 * NDIM + nS;
    const float* zp = wzeros  + (size_t)g0 * NDIM + nS;

    // ---- A staging: 32 rows x 128B = 4KB, 256 threads x 16B ----
    const int ar = tid >> 3, apc = tid & 7;
    const uint4* ap = reinterpret_cast<const uint4*>(
        g_xparts + (size_t)ar * KDIM + g0 * 64 + apc * 8);
    const unsigned aw_off = (unsigned)(ar * A_STRIDE + apc * 16);

    // ---- X sums slice for this k-split (stride 9 to dodge conflicts) ----
    sX[(tid >> 3) * 9 + (tid & 7)] = g_xsum[(tid >> 3) * NCHUNK_G + g0 + (tid & 7)];
    float2 bs = make_float2(0.f, 0.f);
    if (kb == 0) bs = *reinterpret_cast<const float2*>(bias + nS);

    Stage st[2];
    load_stage(st[0], 0, qb, sp, zp, ap);
    {
        char* dst = &sA[0][0] + aw_off;
        *reinterpret_cast<uint4*>(dst) = st[0].a;
    }
    __syncthreads();

    float fin[2][4];
#pragma unroll
    for (int m = 0; m < 2; ++m)
#pragma unroll
        for (int c = 0; c < 4; ++c) fin[m][c] = 0.f;

    const unsigned a_lbase = (unsigned)((lane & 15) * A_STRIDE + (lane >> 4) * 16);

#pragma unroll
    for (int i = 0; i < CPC; ++i) {
        const int cb = i & 1;
        Stage& cur = st[cb];
        if (i + 1 < CPC) load_stage(st[cb ^ 1], i + 1, qb, sp, zp, ap);

        const unsigned Ab = smem_u32(&sA[cb][0]) + a_lbase;
        float acc[2][4];
#pragma unroll
        for (int m = 0; m < 2; ++m)
#pragma unroll
            for (int c = 0; c < 4; ++c) acc[m][c] = 0.f;

        const int qa[8] = { cur.q0.x, cur.q0.y, cur.q0.z, cur.q0.w,
                            cur.q1.x, cur.q1.y, cur.q1.z, cur.q1.w };
#pragma unroll
        for (int s4 = 0; s4 < 4; ++s4) {
            const unsigned b0 = bpack(((unsigned)qa[2 * s4])     >> sh);
            const unsigned b1 = bpack(((unsigned)qa[2 * s4 + 1]) >> sh);
#pragma unroll
            for (int mt = 0; mt < 2; ++mt) {
                unsigned a0, a1, a2, a3;
                ldmatrix_x4(a0, a1, a2, a3,
                            Ab + (unsigned)(mt * 16 * A_STRIDE + s4 * 32));
                mma16816(acc[mt][0], acc[mt][1], acc[mt][2], acc[mt][3],
                         a0, a1, a2, a3, b0, b1);
            }
        }

        // per-group scale + exact-offset correction:
        // out += s*acc - s*(16+z)*X   (X = sum of fp16-rounded x -> 16 cancels)
        const float s0 = cur.s.x, s1 = cur.s.y;
        const float u0 = s0 * (cur.z.x + 16.f);
        const float u1 = s1 * (cur.z.y + 16.f);
        float Xv[4];
#pragma unroll
        for (int jj = 0; jj < 4; ++jj)
            Xv[jj] = sX[((lane >> 2) + 8 * jj) * 9 + i];
#pragma unroll
        for (int mt = 0; mt < 2; ++mt) {
            fin[mt][0] = fmaf(s0, acc[mt][0], fmaf(-u0, Xv[mt * 2 + 0], fin[mt][0]));
            fin[mt][1] = fmaf(s1, acc[mt][1], fmaf(-u1, Xv[mt * 2 + 0], fin[mt][1]));
            fin[mt][2] = fmaf(s0, acc[mt][2], fmaf(-u0, Xv[mt * 2 + 1], fin[mt][2]));
            fin[mt][3] = fmaf(s1, acc[mt][3], fmaf(-u1, Xv[mt * 2 + 1], fin[mt][3]));
        }

        if (i + 1 < CPC) {
            char* dst = &sA[cb ^ 1][0] + aw_off;
            *reinterpret_cast<uint4*>(dst) = st[cb ^ 1].a;
        }
        __syncthreads();
    }

    // ---- epilogue ----
    float* part = &g_partial[kb][0];
#pragma unroll
    for (int mp = 0; mp < 2; ++mp) {
#pragma unroll
        for (int cp = 0; cp < 2; ++cp) {
            int t = mp * 16 + (lane >> 2) + cp * 8;
            float2 o;
            o.x = fin[mp][cp * 2 + 0] + bs.x;
            o.y = fin[mp][cp * 2 + 1] + bs.y;
            *reinterpret_cast<float2*>(part + (size_t)t * NDIM + nS) = o;
        }
    }
}

// ---------------- combine kernel ----------------
__global__ void awq_combine_kernel(float* __restrict__ out) {
    const int j = blockIdx.x * 256 + threadIdx.x;   // < 88064 float4s
    float4 r = reinterpret_cast<const float4*>(g_partial[0])[j];
#pragma unroll
    for (int s = 1; s < SPLITK; ++s) {
        float4 p = reinterpret_cast<const float4*>(g_partial[s])[j];
        r.x += p.x; r.y += p.y; r.z += p.z; r.w += p.w;
    }
    reinterpret_cast<float4*>(out)[j] = r;
}

// ---------------- launch ----------------
extern "C" void kernel_launch(void* const* d_in, const int* in_sizes, int n_in,
                              void* d_out, int out_size) {
    const float* x       = (const float*)d_in[0];
    const int*   qweight = (const int*)d_in[1];
    const float* wscales = (const float*)d_in[2];
    const float* wzeros  = (const float*)d_in[3];
    const float* bias    = (const float*)d_in[4];
    float* out = (float*)d_out;
    (void)in_sizes; (void)n_in; (void)out_size;

    awq_prep_kernel<<<TOK * 4, 256>>>(x);
    awq_main_kernel<<<dim3(GRID_N, SPLITK), 256>>>(qweight, wscales, wzeros, bias);
    awq_combine_kernel<<<(TOK * NDIM) / (256 * 4), 256>>>(out);
}

// round 6
// speedup vs baseline: 3.5707x; 1.0234x over previous
#include <cuda_runtime.h>
#include <cuda_fp16.h>

// ---------------- problem constants ----------------
#define TOK      32
#define KDIM     4096
#define NDIM     11008
#define NTILE    64                  // output columns per CTA
#define GRID_N   (NDIM / NTILE)      // 172
#define SPLITK   8
#define NCHUNK_G 64                  // total k-chunks of 64 (== group size)
#define CPC      (NCHUNK_G / SPLITK) // 8 chunks per CTA
#define KWORDS   2048                // int32 words per packed row
#define XROW     520                 // smem A row stride in halfs (1040B, cf-free)

// x in fp16 (hi only), k PERMUTED within each 64-group:
// orig col c (=k>>1 within group) in [0,32): chat = (c>>3) + 4*(c&7)
__device__ __half g_xparts[TOK * KDIM];
// per-(token, group) sums of the fp16-ROUNDED x (fp32) -> +16 offset cancels
__device__ float  g_xsum[TOK * NCHUNK_G];
__device__ float  g_partial[SPLITK][TOK * NDIM];

// ---------------- prep kernel ----------------
// grid 256 (8 blocks per token), block 256; thread handles 2 contiguous k;
// one warp == one 64-wide quant group.
__global__ void awq_prep_kernel(const float* __restrict__ x) {
    const int blk = blockIdx.x;
    const int tid = threadIdx.x;
    const int t   = blk >> 3;
    const int k0  = (blk & 7) * 512 + tid * 2;
    float2 v = *reinterpret_cast<const float2*>(x + (size_t)t * KDIM + k0);

    __half h0 = __float2half_rn(v.x), h1 = __float2half_rn(v.y);

    int c    = (k0 & 63) >> 1;
    int chat = (c >> 3) + 4 * (c & 7);
    __half* xp = g_xparts + (size_t)t * KDIM + (k0 & ~63);
    *reinterpret_cast<__half2*>(xp + 2 * chat) = __halves2half2(h0, h1);

    float psum = __half2float(h0) + __half2float(h1);
#pragma unroll
    for (int d = 1; d < 32; d <<= 1)
        psum += __shfl_xor_sync(0xFFFFFFFFu, psum, d);
    if ((tid & 31) == 0) {
        int grp = (blk & 7) * 8 + (tid >> 5);
        g_xsum[t * NCHUNK_G + grp] = psum;
    }
}

// ---------------- helpers ----------------
static __device__ __forceinline__ unsigned smem_u32(const void* p) {
    unsigned a;
    asm("{ .reg .u64 t; cvta.to.shared.u64 t, %1; cvt.u32.u64 %0, t; }"
        : "=r"(a) : "l"(p));
    return a;
}
static __device__ __forceinline__ void ldmatrix_x4(unsigned& a0, unsigned& a1,
                                                   unsigned& a2, unsigned& a3,
                                                   unsigned addr) {
    asm volatile("ldmatrix.sync.aligned.m8n8.x4.shared.b16 {%0,%1,%2,%3}, [%4];"
                 : "=r"(a0), "=r"(a1), "=r"(a2), "=r"(a3) : "r"(addr));
}
static __device__ __forceinline__ void mma16816(float& d0, float& d1, float& d2, float& d3,
                                                unsigned a0, unsigned a1, unsigned a2, unsigned a3,
                                                unsigned b0, unsigned b1) {
    asm volatile("mma.sync.aligned.m16n8k16.row.col.f32.f16.f16.f32 "
                 "{%0,%1,%2,%3}, {%4,%5,%6,%7}, {%8,%9}, {%0,%1,%2,%3};"
                 : "+f"(d0), "+f"(d1), "+f"(d2), "+f"(d3)
                 : "r"(a0), "r"(a1), "r"(a2), "r"(a3), "r"(b0), "r"(b1));
}
// fp16 value = 16 + q, bit-exact: 0x4C00 | (q<<6)
static __device__ __forceinline__ unsigned bpack(unsigned t) {
    return 0x4C004C00u | ((t & 0xFu) << 6) | ((t & 0xF0u) << 18);
}

// ---------------- main kernel ----------------
struct Stage {
    int4   q0, q1;   // 8 contiguous packed words (thread's own, post-permute)
    float2 s, z;
};

static __device__ __forceinline__ void load_stage(Stage& st, int i,
        const int* __restrict__ qb, const float* __restrict__ sp,
        const float* __restrict__ zp) {
    st.q0 = *reinterpret_cast<const int4*>(qb + i * 32);
    st.q1 = *reinterpret_cast<const int4*>(qb + i * 32 + 4);
    st.s  = *reinterpret_cast<const float2*>(sp + (size_t)i * NDIM);
    st.z  = *reinterpret_cast<const float2*>(zp + (size_t)i * NDIM);
}

__global__ void __launch_bounds__(256, 3)
awq_main_kernel(const int* __restrict__ qweight,
                const float* __restrict__ wscales,
                const float* __restrict__ wzeros,
                const float* __restrict__ bias) {
    // whole A k-slice for this CTA: 32 rows x 512 halfs (stride 520)
    __shared__ __align__(16) __half sA[32 * XROW];   // 33280 B
    __shared__ float sX[32 * 9];                      // 1152 B

    const int tid  = threadIdx.x;
    const int wid  = tid >> 5;
    const int lane = tid & 31;
    const int n0   = blockIdx.x * NTILE;
    const int kb   = blockIdx.y;
    const int g0   = kb * CPC;

    // ---- B-side: fragment n = n0 + wid*8 + (lane>>2) ----
    const int np      = (n0 >> 2) + 2 * wid + (lane >> 4);   // packed row
    const unsigned sh = 8u * ((lane >> 2) & 3);              // byte select
    const int* qb = qweight + (size_t)np * KWORDS + g0 * 32 + 8 * (lane & 3);

    // ---- accumulator-side n ----
    const int nS = n0 + wid * 8 + 2 * (lane & 3);
    const float* sp = wscales + (size_t)g0 * NDIM + nS;
    const float* zp = wzeros  + (size_t)g0 * NDIM + nS;

    // ---- one-shot A load: 32 rows x 512 halfs = 2048 uint4 ----
    {
        const int r = tid >> 3, pc = tid & 7;
        const uint4* src = reinterpret_cast<const uint4*>(
            g_xparts + (size_t)r * KDIM + g0 * 64) + pc;
        uint4* dst = reinterpret_cast<uint4*>(sA + r * XROW) + pc;
#pragma unroll
        for (int u = 0; u < 8; ++u) dst[u * 8] = src[u * 8];
    }
    // ---- X sums slice (stride 9 to dodge conflicts) ----
    sX[(tid >> 3) * 9 + (tid & 7)] = g_xsum[(tid >> 3) * NCHUNK_G + g0 + (tid & 7)];

    float2 bs = make_float2(0.f, 0.f);
    if (kb == 0) bs = *reinterpret_cast<const float2*>(bias + nS);

    Stage st[2];
    load_stage(st[0], 0, qb, sp, zp);
    __syncthreads();   // the only barrier

    float fin[2][4];
#pragma unroll
    for (int m = 0; m < 2; ++m)
#pragma unroll
        for (int c = 0; c < 4; ++c) fin[m][c] = 0.f;

    const unsigned Abase = smem_u32(sA)
        + (unsigned)(((lane & 15) * XROW + (lane >> 4) * 8) * 2);

#pragma unroll
    for (int i = 0; i < CPC; ++i) {
        const int cb = i & 1;
        Stage& cur = st[cb];
        if (i + 1 < CPC) load_stage(st[cb ^ 1], i + 1, qb, sp, zp);

        float acc[2][4];
#pragma unroll
        for (int m = 0; m < 2; ++m)
#pragma unroll
            for (int c = 0; c < 4; ++c) acc[m][c] = 0.f;

        const int qa[8] = { cur.q0.x, cur.q0.y, cur.q0.z, cur.q0.w,
                            cur.q1.x, cur.q1.y, cur.q1.z, cur.q1.w };
#pragma unroll
        for (int s4 = 0; s4 < 4; ++s4) {
            const unsigned b0 = bpack(((unsigned)qa[2 * s4])     >> sh);
            const unsigned b1 = bpack(((unsigned)qa[2 * s4 + 1]) >> sh);
#pragma unroll
            for (int mt = 0; mt < 2; ++mt) {
                unsigned a0, a1, a2, a3;
                ldmatrix_x4(a0, a1, a2, a3,
                            Abase + (unsigned)((mt * 16 * XROW + i * 64 + s4 * 16) * 2));
                mma16816(acc[mt][0], acc[mt][1], acc[mt][2], acc[mt][3],
                         a0, a1, a2, a3, b0, b1);
            }
        }

        // out += s*acc - s*(16+z)*X   (X = sum of fp16-rounded x -> 16 cancels)
        const float s0 = cur.s.x, s1 = cur.s.y;
        const float u0 = s0 * (cur.z.x + 16.f);
        const float u1 = s1 * (cur.z.y + 16.f);
        float Xv[4];
#pragma unroll
        for (int jj = 0; jj < 4; ++jj)
            Xv[jj] = sX[((lane >> 2) + 8 * jj) * 9 + i];
#pragma unroll
        for (int mt = 0; mt < 2; ++mt) {
            fin[mt][0] = fmaf(s0, acc[mt][0], fmaf(-u0, Xv[mt * 2 + 0], fin[mt][0]));
            fin[mt][1] = fmaf(s1, acc[mt][1], fmaf(-u1, Xv[mt * 2 + 0], fin[mt][1]));
            fin[mt][2] = fmaf(s0, acc[mt][2], fmaf(-u0, Xv[mt * 2 + 1], fin[mt][2]));
            fin[mt][3] = fmaf(s1, acc[mt][3], fmaf(-u1, Xv[mt * 2 + 1], fin[mt][3]));
        }
    }

    // ---- epilogue ----
    float* part = &g_partial[kb][0];
#pragma unroll
    for (int mp = 0; mp < 2; ++mp) {
#pragma unroll
        for (int cp = 0; cp < 2; ++cp) {
            int t = mp * 16 + (lane >> 2) + cp * 8;
            float2 o;
            o.x = fin[mp][cp * 2 + 0] + bs.x;
            o.y = fin[mp][cp * 2 + 1] + bs.y;
            *reinterpret_cast<float2*>(part + (size_t)t * NDIM + nS) = o;
        }
    }
}

// ---------------- combine kernel ----------------
__global__ void awq_combine_kernel(float* __restrict__ out) {
    const int j = blockIdx.x * 256 + threadIdx.x;   // < 88064 float4s
    float4 r = reinterpret_cast<const float4*>(g_partial[0])[j];
#pragma unroll
    for (int s = 1; s < SPLITK; ++s) {
        float4 p = reinterpret_cast<const float4*>(g_partial[s])[j];
        r.x += p.x; r.y += p.y; r.z += p.z; r.w += p.w;
    }
    reinterpret_cast<float4*>(out)[j] = r;
}

// ---------------- launch ----------------
extern "C" void kernel_launch(void* const* d_in, const int* in_sizes, int n_in,
                              void* d_out, int out_size) {
    const float* x       = (const float*)d_in[0];
    const int*   qweight = (const int*)d_in[1];
    const float* wscales = (const float*)d_in[2];
    const float* wzeros  = (const float*)d_in[3];
    const float* bias    = (const float*)d_in[4];
    float* out = (float*)d_out;
    (void)in_sizes; (void)n_in; (void)out_size;

    awq_prep_kernel<<<TOK * 8, 256>>>(x);
    awq_main_kernel<<<dim3(GRID_N, SPLITK), 256>>>(qweight, wscales, wzeros, bias);
    awq_combine_kernel<<<(TOK * NDIM) / (256 * 4), 256>>>(out);
}